// round 8
// baseline (speedup 1.0000x reference)
#include <cuda_runtime.h>
#include <cuda_bf16.h>

// CTC forward: one block (128 threads = 4 warps) per batch element.
// Thread i owns pair (E_i = state 2i, O_i = state 2i+1) in registers.
// THREE time steps per __syncthreads via halo: thread i redundantly advances
// O_{i-1}, E_{i-1}, O_{i-2} so steps 2 and 3 need no fresh remote data.
// Shared-max lse: one fmax3 per state-pair update, skip handled as a 0/1
// multiply. Alphas in log2 domain; ex2/lg2 raw MUFU.

#define NEGF  (-1e30f)
#define LOG2E 1.4426950408889634f
#define LN2   0.6931471805599453f
#define MAXB  1024

__device__ float        g_per_ex[MAXB];
__device__ unsigned int g_count = 0;

__device__ __forceinline__ float ex2(float x) { float r; asm("ex2.approx.f32 %0, %1;" : "=f"(r) : "f"(x)); return r; }
__device__ __forceinline__ float lg2(float x) { float r; asm("lg2.approx.f32 %0, %1;" : "=f"(r) : "f"(x)); return r; }
__device__ __forceinline__ float fmax3(float a, float b, float c) { return fmaxf(fmaxf(a, b), c); }

__device__ __forceinline__ float lse2(float a, float b) {
    float m = fmaxf(a, b);
    float d = fminf(a, b) - m;
    return m + lg2(1.0f + ex2(d));
}

struct Emi { float v[9]; };  // [eb,el,em1,em2, eb,el,em1, eb,el] for 3 steps

__device__ __forceinline__ void load_emi(const float* __restrict__ rowp, int C,
                                         int t0, int steps, int lbl, int c1, int c2,
                                         Emi& e)
{
    int ta = t0;     if (ta > steps) ta = steps; if (ta < 0) ta = 0;
    int tb = t0 + 1; if (tb > steps) tb = steps; if (tb < 0) tb = 0;
    int tc = t0 + 2; if (tc > steps) tc = steps; if (tc < 0) tc = 0;
    const float* pa = rowp + (size_t)ta * C;
    const float* pb = rowp + (size_t)tb * C;
    const float* pc = rowp + (size_t)tc * C;
    e.v[0] = __ldg(pa)       * LOG2E;
    e.v[1] = __ldg(pa + lbl) * LOG2E;
    e.v[2] = __ldg(pa + c1)  * LOG2E;
    e.v[3] = __ldg(pa + c2)  * LOG2E;
    e.v[4] = __ldg(pb)       * LOG2E;
    e.v[5] = __ldg(pb + lbl) * LOG2E;
    e.v[6] = __ldg(pb + c1)  * LOG2E;
    e.v[7] = __ldg(pc)       * LOG2E;
    e.v[8] = __ldg(pc + lbl) * LOG2E;
}

__global__ __launch_bounds__(128, 1)
void ctc_forward_kernel(const float* __restrict__ pred,           // (B, T, C)
                        const int*   __restrict__ targets,        // (B, L)
                        const int*   __restrict__ pred_lengths,   // (B,)
                        const int*   __restrict__ target_lengths, // (B,)
                        float*       __restrict__ out,
                        int T, int C, int L, int B)
{
    // (E_i, O_i) at [i+3]; [0..2] = (NEG,NEG) sentinels (serve i-1, i-2, i-3).
    __shared__ float2 sEO[2][132];
    __shared__ float sOf[128];
    __shared__ float sEf[129];
    __shared__ unsigned int s_last;
    __shared__ float sred[4];

    const int b    = blockIdx.x;
    const int i    = threadIdx.x;        // pair index 0..127
    const int w    = i >> 5;
    const int lane = i & 31;

    const int  li    = (i < L) ? i : (L - 1);
    const int  lbl   = targets[(size_t)b * L + li];
    const int  lblm1 = (li >= 1) ? targets[(size_t)b * L + li - 1] : -1;
    const int  lblm2 = (li >= 2) ? targets[(size_t)b * L + li - 2] : -1;
    const int  lblm3 = (li >= 3) ? targets[(size_t)b * L + li - 3] : -1;
    const float skf   = ((lbl   != 0) && (lbl   != lblm1)) ? 1.0f : 0.0f;
    const float skm1f = ((li >= 1) && (lblm1 != 0) && (lblm1 != lblm2)) ? 1.0f : 0.0f;
    const float skm2f = ((li >= 2) && (lblm2 != 0) && (lblm2 != lblm3)) ? 1.0f : 0.0f;
    const int  c1 = (li >= 1) ? lblm1 : 0;
    const int  c2 = (li >= 2) ? lblm2 : 0;

    const float* rowp = pred + (size_t)b * T * C;

    int pl = pred_lengths[b];
    int Teff = pl < T ? pl : T; if (Teff < 1) Teff = 1;
    const int steps = Teff - 1;          // updates at t = 1..steps

    // ---- init (t = 0) ----
    float eb0 = __ldg(rowp) * LOG2E;
    float el0 = __ldg(rowp + lbl) * LOG2E;
    float E  = (i == 0) ? eb0 : NEGF;
    float O  = (i == 0) ? el0 : NEGF;
    float E2g = NEGF;                    // state 2L (thread 127, used iff tl==L)

    if (i < 3) { sEO[0][i] = make_float2(NEGF, NEGF); sEO[1][i] = make_float2(NEGF, NEGF); }
    sEO[0][i + 3] = make_float2(E, O);

    // emission double buffer: e0 = even rounds (parity 0), e1 = odd rounds
    Emi e0, e1;
    load_emi(rowp, C, 1, steps, lbl, c1, c2, e0);   // round at t=1
    load_emi(rowp, C, 4, steps, lbl, c1, c2, e1);   // round at t=4

    __syncthreads();

    int t = 1;

#define ROUND(P, EMI, TNEXT)                                                    \
    {                                                                           \
        float2 n1 = sEO[P][i + 2];  /* (E_{i-1}, O_{i-1}) */                    \
        float2 n2 = sEO[P][i + 1];  /* (E_{i-2}, O_{i-2}) */                    \
        float2 n3 = sEO[P][i];      /* (.,       O_{i-3}) */                    \
        float Em1 = n1.x, Om1 = n1.y, Em2 = n2.x, Om2 = n2.y, Om3 = n3.y;       \
        /* ---- step 1 ---- */                                                  \
        float m  = fmax3(E, O, Om1);                                            \
        float xE = ex2(E - m), xO = ex2(O - m), xM = ex2(Om1 - m);              \
        float E1 = m + lg2(xE + xM) + EMI.v[0];                                 \
        float O1 = m + lg2(xO + xE + skf * xM) + EMI.v[1];                      \
        float ma  = fmax3(Em1, Om1, Om2);                                       \
        float xEa = ex2(Em1 - ma), xOa = ex2(Om1 - ma), xMa = ex2(Om2 - ma);    \
        float Em1_1 = ma + lg2(xEa + xMa) + EMI.v[0];                           \
        float Om1_1 = ma + lg2(xOa + xEa + skm1f * xMa) + EMI.v[2];             \
        float mb  = fmax3(Om2, Em2, Om3);                                       \
        float Om2_1 = mb + lg2(ex2(Om2 - mb) + ex2(Em2 - mb)                    \
                               + skm2f * ex2(Om3 - mb)) + EMI.v[3];             \
        /* ---- step 2 ---- */                                                  \
        float m2  = fmax3(E1, O1, Om1_1);                                       \
        float yE = ex2(E1 - m2), yO = ex2(O1 - m2), yM = ex2(Om1_1 - m2);       \
        float E2s = m2 + lg2(yE + yM) + EMI.v[4];                               \
        float O2  = m2 + lg2(yO + yE + skf * yM) + EMI.v[5];                    \
        float mc  = fmax3(Om1_1, Em1_1, Om2_1);                                 \
        float Om1_2 = mc + lg2(ex2(Om1_1 - mc) + ex2(Em1_1 - mc)                \
                               + skm1f * ex2(Om2_1 - mc)) + EMI.v[6];           \
        /* ---- step 3 ---- */                                                  \
        float m3  = fmax3(E2s, O2, Om1_2);                                      \
        float zE = ex2(E2s - m3), zO = ex2(O2 - m3), zM = ex2(Om1_2 - m3);      \
        float E3 = m3 + lg2(zE + zM) + EMI.v[7];                                \
        float O3 = m3 + lg2(zO + zE + skf * zM) + EMI.v[8];                     \
        sEO[(P) ^ 1][i + 3] = make_float2(E3, O3);                              \
        if (i == 127) {                                                         \
            E2g = lse2(E2g, O)  + EMI.v[0];                                     \
            E2g = lse2(E2g, O1) + EMI.v[4];                                     \
            E2g = lse2(E2g, O2) + EMI.v[7];                                     \
        }                                                                       \
        E = E3; O = O3;                                                         \
        load_emi(rowp, C, (TNEXT), steps, lbl, c1, c2, EMI);                    \
        __syncthreads();                                                        \
    }

    // ---- main loop: two rounds (6 steps) per iteration ----
    for (; t + 5 <= steps; t += 6) {
        ROUND(0, e0, t + 6);
        { const int tb2 = t + 3; (void)tb2; }
        ROUND(1, e1, t + 9);
    }
#undef ROUND

    // ---- tail: single-step rounds (<= 5 remaining), runtime parity ----
    {
        int rb = 0;
        for (; t <= steps; t++) {
            const float* pp = rowp + (size_t)t * C;
            float ebx = __ldg(pp) * LOG2E;
            float elx = __ldg(pp + lbl) * LOG2E;
            float Om1 = sEO[rb][i + 2].y;
            if (i == 127) E2g = lse2(E2g, O) + ebx;
            float m  = fmax3(E, O, Om1);
            float xE = ex2(E - m), xO = ex2(O - m), xM = ex2(Om1 - m);
            float nE = m + lg2(xE + xM) + ebx;
            float nO = m + lg2(xO + xE + skf * xM) + elx;
            sEO[rb ^ 1][i + 3] = make_float2(nE, nO);
            E = nE; O = nO;
            rb ^= 1;
            __syncthreads();
        }
    }

    // ---- gather + per-example loss ----
    sOf[i] = O;
    sEf[i] = E;
    if (i == 127) sEf[128] = E2g;
    __syncthreads();

    if (i == 0) {
        int tl = target_lengths[b];
        int tlc = tl; if (tlc < 1) tlc = 1; if (tlc > L) tlc = L;
        float l1 = sOf[tlc - 1];        // state 2*tl - 1
        float l2 = sEf[tlc];            // state 2*tl
        float per = -(lse2(l1, l2) * LN2);
        if (per > 1e29f) per = 0.0f;
        int denom = tl < 1 ? 1 : tl;
        g_per_ex[b] = per / (float)denom;
        __threadfence();
        unsigned prevc = atomicAdd(&g_count, 1u);
        s_last = (prevc == (unsigned)(B - 1)) ? 1u : 0u;
    }
    __syncthreads();

    // ---- last block computes the batch mean (deterministic fixed order) ----
    if (s_last) {
        float v = 0.f;
        for (int idx = i; idx < B; idx += 128)
            v += *((volatile float*)&g_per_ex[idx]);
#pragma unroll
        for (int o = 16; o > 0; o >>= 1)
            v += __shfl_down_sync(0xffffffffu, v, o);
        if (lane == 0) sred[w] = v;
        __syncthreads();
        if (i == 0) {
            float tot = sred[0] + sred[1] + sred[2] + sred[3];
            out[0] = tot / (float)B;
            g_count = 0;    // reset for next graph replay
        }
    }
}

extern "C" void kernel_launch(void* const* d_in, const int* in_sizes, int n_in,
                              void* d_out, int out_size)
{
    const float* pred           = (const float*)d_in[0];
    const int*   targets        = (const int*)d_in[1];
    const int*   pred_lengths   = (const int*)d_in[2];
    const int*   target_lengths = (const int*)d_in[3];

    const int B = in_sizes[2];
    const int L = in_sizes[1] / B;
    const int C = 128;
    const int T = (in_sizes[0] / B) / C;

    ctc_forward_kernel<<<B, 128>>>(pred, targets, pred_lengths, target_lengths,
                                   (float*)d_out, T, C, L, B);
}

// round 10
// speedup vs baseline: 1.9199x; 1.9199x over previous
#include <cuda_runtime.h>
#include <cuda_bf16.h>

// CTC forward in LINEAR domain with PER-THREAD exponent scaling.
// One warp (32 threads) per batch element; thread owns 4 pairs
// (E_p = state 2p, O_p = state 2p+1), p = 4*lane+k; lane 31 also owns E_128.
// alpha_s(t) = (alpha_s + alpha_{s-1} + skip*alpha_{s-2})(t-1) * ratio_s(t),
// emissions normalized by the blank column (blank ratio == 1) -> pure FMA.
// Each thread renormalizes its 9 states by an exact power of 2 every 4 steps
// (also every tail step) and tracks exponent e_i; the single cross-thread
// value per step is rescaled by 2^(e_{i-1}-e_i). No barriers in the loop.

#define LOG2E 1.4426950408889634f
#define LN2   0.6931471805599453f
#define FULLM 0xffffffffu
#define MAXB  4096

__device__ float        g_per_ex[MAXB];
__device__ unsigned int g_count = 0;

__device__ __forceinline__ float ex2f_(float x){ float r; asm("ex2.approx.f32 %0,%1;" : "=f"(r) : "f"(x)); return r; }
__device__ __forceinline__ float lg2f_(float x){ float r; asm("lg2.approx.f32 %0,%1;" : "=f"(r) : "f"(x)); return r; }

__global__ __launch_bounds__(32, 1)
void ctc_forward_kernel(const float* __restrict__ pred,           // (B, T, C)
                        const int*   __restrict__ targets,        // (B, L)
                        const int*   __restrict__ pred_lengths,   // (B,)
                        const int*   __restrict__ target_lengths, // (B,)
                        float*       __restrict__ out,
                        int T, int C, int L, int B)
{
    __shared__ float sE[129];
    __shared__ float sO[128];
    __shared__ int   sExp[32];
    __shared__ unsigned int s_last;

    const int b    = blockIdx.x;
    const int lane = threadIdx.x;
    const int p0   = lane * 4;

    int   cols[4]; float sk[4], vm[4];
#pragma unroll
    for (int k = 0; k < 4; k++) {
        int p  = p0 + k;
        int li = (p < L) ? p : (L - 1);
        int l  = targets[(size_t)b * L + li];
        int pr = (li >= 1) ? targets[(size_t)b * L + li - 1] : -1;
        cols[k] = l;
        sk[k] = (l != 0 && l != pr) ? 1.f : 0.f;
        vm[k] = (p < L) ? 1.f : 0.f;        // O_p valid iff p < L
    }

    const float* rowp = pred + (size_t)b * T * C;
    int pl = pred_lengths[b];
    int Teff = pl < T ? pl : T; if (Teff < 1) Teff = 1;
    const int steps = Teff - 1;              // updates at t = 1..steps

    // ---- init (t = 0), emissions normalized by blank column ----
    float eb0l2 = __ldg(rowp) * LOG2E;
    float ebsum = eb0l2;                     // sum of blank log2-probs (uniform)
    float E0=0.f,E1=0.f,E2=0.f,E3=0.f, O0=0.f,O1=0.f,O2=0.f,O3=0.f, EX=0.f;
    if (lane == 0) {
        E0 = 1.f;
        O0 = ex2f_(fmaf(__ldg(rowp + cols[0]), LOG2E, -eb0l2)) * vm[0];
    }
    int   e_i = 0;              // per-thread exponent: true alpha = val * 2^e_i
    float scale_in = 1.f;       // 2^(e_{lane-1} - e_lane)

    // per-thread exact power-of-2 renorm + boundary-scale refresh
#define RENORM()                                                            \
    {                                                                       \
        float m = fmaxf(fmaxf(fmaxf(E0,E1), fmaxf(E2,E3)),                  \
                        fmaxf(fmaxf(O0,O1), fmaxf(O2,O3)));                 \
        m = fmaxf(m, EX);                                                   \
        int ee = 0;                                                         \
        if (m > 0.f) ee = (int)((__float_as_uint(m) >> 23) & 0xffu) - 127;  \
        float sc = __uint_as_float((unsigned)(127 - ee) << 23);             \
        E0*=sc; E1*=sc; E2*=sc; E3*=sc;                                     \
        O0*=sc; O1*=sc; O2*=sc; O3*=sc; EX*=sc;                             \
        e_i += ee;                                                          \
        int ep = __shfl_up_sync(FULLM, e_i, 1);                             \
        int de = ep - e_i;                                                  \
        de = de > 126 ? 126 : (de < -126 ? -126 : de);                      \
        scale_in = __uint_as_float((unsigned)(127 + de) << 23);             \
    }

    // emission ratio ring, depth 8
    float4 rr[8]; float eb2[8];
#pragma unroll
    for (int j = 0; j < 8; j++) {
        int tt = 1 + j; if (tt > steps) tt = steps; if (tt < 0) tt = 0;
        const float* pp = rowp + (size_t)tt * C;
        float ebv = __ldg(pp) * LOG2E;
        rr[j].x = ex2f_(fmaf(__ldg(pp + cols[0]), LOG2E, -ebv)) * vm[0];
        rr[j].y = ex2f_(fmaf(__ldg(pp + cols[1]), LOG2E, -ebv)) * vm[1];
        rr[j].z = ex2f_(fmaf(__ldg(pp + cols[2]), LOG2E, -ebv)) * vm[2];
        rr[j].w = ex2f_(fmaf(__ldg(pp + cols[3]), LOG2E, -ebv)) * vm[3];
        eb2[j] = ebv;
    }

    int t = 1;
    for (; t + 7 <= steps; t += 8) {
#pragma unroll
        for (int j = 0; j < 8; j++) {
            float Om1 = __shfl_up_sync(FULLM, O3, 1);
            Om1 = (lane == 0) ? 0.f : Om1 * scale_in;
            float nO0 = fmaf(sk[0], Om1, O0 + E0) * rr[j].x;
            float nE0 = E0 + Om1;
            float nO1 = fmaf(sk[1], O0, O1 + E1) * rr[j].y;
            float nE1 = E1 + O0;
            float nO2 = fmaf(sk[2], O1, O2 + E2) * rr[j].z;
            float nE2 = E2 + O1;
            float nO3 = fmaf(sk[3], O2, O3 + E3) * rr[j].w;
            float nE3 = E3 + O2;
            float nEX = (lane == 31) ? (EX + O3) : 0.f;   // state 2L (blank, ratio 1)
            ebsum += eb2[j];
            O0=nO0; O1=nO1; O2=nO2; O3=nO3;
            E0=nE0; E1=nE1; E2=nE2; E3=nE3; EX=nEX;
            // prefetch step t+8+j into slot j (off-chain)
            int tn = t + 8 + j; if (tn > steps) tn = steps;
            const float* pp = rowp + (size_t)tn * C;
            float ebv = __ldg(pp) * LOG2E;
            rr[j].x = ex2f_(fmaf(__ldg(pp + cols[0]), LOG2E, -ebv)) * vm[0];
            rr[j].y = ex2f_(fmaf(__ldg(pp + cols[1]), LOG2E, -ebv)) * vm[1];
            rr[j].z = ex2f_(fmaf(__ldg(pp + cols[2]), LOG2E, -ebv)) * vm[2];
            rr[j].w = ex2f_(fmaf(__ldg(pp + cols[3]), LOG2E, -ebv)) * vm[3];
            eb2[j] = ebv;
            if (j == 3 || j == 7) RENORM();
        }
    }
    // ---- tail (< 8 steps), direct loads, renorm EVERY step ----
    for (; t <= steps; t++) {
        const float* pp = rowp + (size_t)t * C;
        float ebv = __ldg(pp) * LOG2E;
        float r0 = ex2f_(fmaf(__ldg(pp + cols[0]), LOG2E, -ebv)) * vm[0];
        float r1 = ex2f_(fmaf(__ldg(pp + cols[1]), LOG2E, -ebv)) * vm[1];
        float r2 = ex2f_(fmaf(__ldg(pp + cols[2]), LOG2E, -ebv)) * vm[2];
        float r3 = ex2f_(fmaf(__ldg(pp + cols[3]), LOG2E, -ebv)) * vm[3];
        float Om1 = __shfl_up_sync(FULLM, O3, 1);
        Om1 = (lane == 0) ? 0.f : Om1 * scale_in;
        float nO0 = fmaf(sk[0], Om1, O0 + E0) * r0;
        float nE0 = E0 + Om1;
        float nO1 = fmaf(sk[1], O0, O1 + E1) * r1;
        float nE1 = E1 + O0;
        float nO2 = fmaf(sk[2], O1, O2 + E2) * r2;
        float nE2 = E2 + O1;
        float nO3 = fmaf(sk[3], O2, O3 + E3) * r3;
        float nE3 = E3 + O2;
        float nEX = (lane == 31) ? (EX + O3) : 0.f;
        ebsum += ebv;
        O0=nO0; O1=nO1; O2=nO2; O3=nO3;
        E0=nE0; E1=nE1; E2=nE2; E3=nE3; EX=nEX;
        RENORM();
    }
#undef RENORM

    // ---- gather + per-example loss (log2 domain, per-state exponents) ----
    sO[p0+0]=O0; sO[p0+1]=O1; sO[p0+2]=O2; sO[p0+3]=O3;
    sE[p0+0]=E0; sE[p0+1]=E1; sE[p0+2]=E2; sE[p0+3]=E3;
    if (lane == 31) sE[128] = EX;
    sExp[lane] = e_i;
    __syncwarp();

    if (lane == 0) {
        int tl = target_lengths[b];
        int tlc = tl; if (tlc < 1) tlc = 1; if (tlc > L) tlc = L;
        float l1v = sO[tlc - 1];                       // state 2*tl - 1
        int   e1  = sExp[(tlc - 1) >> 2];
        float l2v = sE[tlc];                           // state 2*tl
        int   e2  = (tlc < 128) ? sExp[tlc >> 2] : sExp[31];
        float g1 = lg2f_(l1v) + (float)e1;             // -inf if l1v == 0
        float g2 = lg2f_(l2v) + (float)e2;
        float mm = fmaxf(g1, g2);
        float dd = fminf(g1, g2) - mm;
        float logv = mm + lg2f_(1.f + ex2f_(dd)) + ebsum;   // log2 P
        float per = -LN2 * logv;
        if (!(per < 1e29f)) per = 0.f;                 // zero_infinity (+inf/NaN)
        int den = tl < 1 ? 1 : tl;
        g_per_ex[b] = per / (float)den;
        __threadfence();
        unsigned pc = atomicAdd(&g_count, 1u);
        s_last = (pc == (unsigned)(B - 1)) ? 1u : 0u;
    }
    __syncwarp();

    // ---- last block computes the batch mean (deterministic fixed order) ----
    if (s_last) {
        float v = 0.f;
        for (int idx = lane; idx < B; idx += 32)
            v += *((volatile float*)&g_per_ex[idx]);
#pragma unroll
        for (int o = 16; o > 0; o >>= 1)
            v += __shfl_down_sync(FULLM, v, o);
        if (lane == 0) { out[0] = v / (float)B; g_count = 0u; }
    }
}

extern "C" void kernel_launch(void* const* d_in, const int* in_sizes, int n_in,
                              void* d_out, int out_size)
{
    const float* pred           = (const float*)d_in[0];
    const int*   targets        = (const int*)d_in[1];
    const int*   pred_lengths   = (const int*)d_in[2];
    const int*   target_lengths = (const int*)d_in[3];

    const int B = in_sizes[2];
    const int L = in_sizes[1] / B;
    const int C = 128;
    const int T = (in_sizes[0] / B) / C;

    ctc_forward_kernel<<<B, 32>>>(pred, targets, pred_lengths, target_lengths,
                                  (float*)d_out, T, C, L, B);
}

// round 11
// speedup vs baseline: 3.6836x; 1.9186x over previous
#include <cuda_runtime.h>
#include <cuda_bf16.h>

// CTC forward, LINEAR domain, per-thread exponent scaling, WARP-SPECIALIZED.
// One block (96 threads) per batch element:
//   warp 0  = consumer: lattice recurrence only (LDS ratios + shfl + FMA).
//   warps 1,2 = producers: emission ratios (LDG + ex2) into a double-buffered
//               smem ring; each handles 8 of every 16 steps.
// One __syncthreads per 16 steps. Thread owns 4 pairs (E_p=2p, O_p=2p+1).
// alpha_s(t) = (alpha_s + alpha_{s-1} + skip*alpha_{s-2})(t-1) * ratio,
// emissions normalized by blank (blank ratio == 1). Per-thread power-of-2
// renorm every 4 steps; exponent folded back at readout.

#define LOG2E 1.4426950408889634f
#define LN2   0.6931471805599453f
#define FULLM 0xffffffffu
#define MAXB  4096
#define CH    16

__device__ float        g_per_ex[MAXB];
__device__ unsigned int g_count = 0;

__device__ __forceinline__ float ex2f_(float x){ float r; asm("ex2.approx.f32 %0,%1;" : "=f"(r) : "f"(x)); return r; }
__device__ __forceinline__ float lg2f_(float x){ float r; asm("lg2.approx.f32 %0,%1;" : "=f"(r) : "f"(x)); return r; }

__global__ __launch_bounds__(96, 1)
void ctc_forward_kernel(const float* __restrict__ pred,           // (B, T, C)
                        const int*   __restrict__ targets,        // (B, L)
                        const int*   __restrict__ pred_lengths,   // (B,)
                        const int*   __restrict__ target_lengths, // (B,)
                        float*       __restrict__ out,
                        int T, int C, int L, int B)
{
    __shared__ float4 ring[2][CH][32];     // [buf][step-in-chunk][lane]
    __shared__ float sE[129];
    __shared__ float sO[128];
    __shared__ int   sExp[32];
    __shared__ float s_eb[2];
    __shared__ unsigned int s_last;

    const int b   = blockIdx.x;
    const int tid = threadIdx.x;
    const int wid = tid >> 5;              // 0 consumer, 1..2 producers
    const int wl  = tid & 31;
    const int p0  = wl * 4;

    int   cols[4]; float sk[4], vm[4];
#pragma unroll
    for (int k = 0; k < 4; k++) {
        int p  = p0 + k;
        int li = (p < L) ? p : (L - 1);
        int l  = targets[(size_t)b * L + li];
        int pr = (li >= 1) ? targets[(size_t)b * L + li - 1] : -1;
        cols[k] = l;
        sk[k] = (l != 0 && l != pr) ? 1.f : 0.f;
        vm[k] = (p < L) ? 1.f : 0.f;
    }

    const float* rowp = pred + (size_t)b * T * C;
    int pl = pred_lengths[b];
    int Teff = pl < T ? pl : T; if (Teff < 1) Teff = 1;
    const int steps = Teff - 1;            // updates at t = 1..steps
    const int nch   = steps / CH;          // full 16-step chunks
    const int ps    = nch * CH;            // produced steps: t = 1..ps

    // ---- consumer state ----
    float E0=0.f,E1=0.f,E2=0.f,E3=0.f, O0=0.f,O1=0.f,O2=0.f,O3=0.f, EX=0.f;
    int   e_i = 0;
    float scale_in = 1.f;
    float cebs = 0.f;                      // consumer's remainder eb sum
    if (wid == 0 && wl == 0) {
        float eb0l2 = __ldg(rowp) * LOG2E;
        E0 = 1.f;
        O0 = ex2f_(fmaf(__ldg(rowp + cols[0]), LOG2E, -eb0l2)) * vm[0];
    }

#define RENORM()                                                            \
    {                                                                       \
        float m = fmaxf(fmaxf(fmaxf(E0,E1), fmaxf(E2,E3)),                  \
                        fmaxf(fmaxf(O0,O1), fmaxf(O2,O3)));                 \
        m = fmaxf(m, EX);                                                   \
        int ee = 0;                                                         \
        if (m > 0.f) ee = (int)((__float_as_uint(m) >> 23) & 0xffu) - 127;  \
        float sc = __uint_as_float((unsigned)(127 - ee) << 23);             \
        E0*=sc; E1*=sc; E2*=sc; E3*=sc;                                     \
        O0*=sc; O1*=sc; O2*=sc; O3*=sc; EX*=sc;                             \
        e_i += ee;                                                          \
        int ep = __shfl_up_sync(FULLM, e_i, 1);                             \
        int de = ep - e_i;                                                  \
        de = de > 126 ? 126 : (de < -126 ? -126 : de);                      \
        scale_in = __uint_as_float((unsigned)(127 + de) << 23);             \
    }

    // ---- producer state: raw loads for this producer's share of next chunk ----
    float rb_[8], r0_[8], r1_[8], r2_[8], r3_[8];
    float pebs = 0.f;
    if (wid >= 1) {
        if (wid == 1) pebs = __ldg(rowp) * LOG2E;      // t = 0 blank term
#pragma unroll
        for (int jj = 0; jj < 8; jj++) {
            int tt = (wid - 1) * 8 + jj + 1;           // chunk 0 share
            if (tt > ps) tt = ps > 0 ? ps : 1;
            const float* pp = rowp + (size_t)(ps > 0 ? tt : 0) * C;
            rb_[jj] = __ldg(pp);
            r0_[jj] = __ldg(pp + cols[0]);
            r1_[jj] = __ldg(pp + cols[1]);
            r2_[jj] = __ldg(pp + cols[2]);
            r3_[jj] = __ldg(pp + cols[3]);
        }
    }

    // ---- phase loop: producers fill chunk p, consumer eats chunk p-1 ----
    for (int p = 0; p <= nch; p++) {
        if (wid >= 1) {
            if (p < nch) {
#pragma unroll
                for (int jj = 0; jj < 8; jj++) {
                    const int j = (wid - 1) * 8 + jj;
                    float ebv = rb_[jj] * LOG2E;
                    float4 o;
                    o.x = ex2f_(fmaf(r0_[jj], LOG2E, -ebv)) * vm[0];
                    o.y = ex2f_(fmaf(r1_[jj], LOG2E, -ebv)) * vm[1];
                    o.z = ex2f_(fmaf(r2_[jj], LOG2E, -ebv)) * vm[2];
                    o.w = ex2f_(fmaf(r3_[jj], LOG2E, -ebv)) * vm[3];
                    ring[p & 1][j][wl] = o;
                    pebs += ebv;
                }
                // preload share of chunk p+1
#pragma unroll
                for (int jj = 0; jj < 8; jj++) {
                    int tn = (p + 1) * CH + (wid - 1) * 8 + jj + 1;
                    if (tn > ps) tn = ps;
                    const float* pp = rowp + (size_t)tn * C;
                    rb_[jj] = __ldg(pp);
                    r0_[jj] = __ldg(pp + cols[0]);
                    r1_[jj] = __ldg(pp + cols[1]);
                    r2_[jj] = __ldg(pp + cols[2]);
                    r3_[jj] = __ldg(pp + cols[3]);
                }
            }
        } else if (p >= 1) {
            const int buf = (p - 1) & 1;
#pragma unroll
            for (int j = 0; j < CH; j++) {
                float4 r = ring[buf][j][wl];
                float Om1 = __shfl_up_sync(FULLM, O3, 1);
                Om1 = (wl == 0) ? 0.f : Om1 * scale_in;
                float nO0 = fmaf(sk[0], Om1, O0 + E0) * r.x;
                float nE0 = E0 + Om1;
                float nO1 = fmaf(sk[1], O0, O1 + E1) * r.y;
                float nE1 = E1 + O0;
                float nO2 = fmaf(sk[2], O1, O2 + E2) * r.z;
                float nE2 = E2 + O1;
                float nO3 = fmaf(sk[3], O2, O3 + E3) * r.w;
                float nE3 = E3 + O2;
                float nEX = (wl == 31) ? (EX + O3) : 0.f;   // state 2L, blank ratio 1
                O0=nO0; O1=nO1; O2=nO2; O3=nO3;
                E0=nE0; E1=nE1; E2=nE2; E3=nE3; EX=nEX;
                if ((j & 3) == 3) RENORM();
            }
        }
        __syncthreads();
    }

    // ---- remainder (t = ps+1 .. steps), consumer solo, direct loads ----
    if (wid == 0) {
        for (int t = ps + 1; t <= steps; t++) {
            const float* pp = rowp + (size_t)t * C;
            float ebv = __ldg(pp) * LOG2E;
            float rx = ex2f_(fmaf(__ldg(pp + cols[0]), LOG2E, -ebv)) * vm[0];
            float ry = ex2f_(fmaf(__ldg(pp + cols[1]), LOG2E, -ebv)) * vm[1];
            float rz = ex2f_(fmaf(__ldg(pp + cols[2]), LOG2E, -ebv)) * vm[2];
            float rw = ex2f_(fmaf(__ldg(pp + cols[3]), LOG2E, -ebv)) * vm[3];
            float Om1 = __shfl_up_sync(FULLM, O3, 1);
            Om1 = (wl == 0) ? 0.f : Om1 * scale_in;
            float nO0 = fmaf(sk[0], Om1, O0 + E0) * rx;
            float nE0 = E0 + Om1;
            float nO1 = fmaf(sk[1], O0, O1 + E1) * ry;
            float nE1 = E1 + O0;
            float nO2 = fmaf(sk[2], O1, O2 + E2) * rz;
            float nE2 = E2 + O1;
            float nO3 = fmaf(sk[3], O2, O3 + E3) * rw;
            float nE3 = E3 + O2;
            float nEX = (wl == 31) ? (EX + O3) : 0.f;
            cebs += ebv;
            O0=nO0; O1=nO1; O2=nO2; O3=nO3;
            E0=nE0; E1=nE1; E2=nE2; E3=nE3; EX=nEX;
            RENORM();
        }
        // gather
        sO[p0+0]=O0; sO[p0+1]=O1; sO[p0+2]=O2; sO[p0+3]=O3;
        sE[p0+0]=E0; sE[p0+1]=E1; sE[p0+2]=E2; sE[p0+3]=E3;
        if (wl == 31) sE[128] = EX;
        sExp[wl] = e_i;
    } else if (wl == 0) {
        s_eb[wid - 1] = pebs;
    }
#undef RENORM
    __syncthreads();

    if (tid == 0) {
        float ebsum = s_eb[0] + s_eb[1] + cebs;
        int tl = target_lengths[b];
        int tlc = tl; if (tlc < 1) tlc = 1; if (tlc > L) tlc = L;
        float l1v = sO[tlc - 1];                       // state 2*tl - 1
        int   e1  = sExp[(tlc - 1) >> 2];
        float l2v = sE[tlc];                           // state 2*tl
        int   e2  = (tlc < 128) ? sExp[tlc >> 2] : sExp[31];
        float g1 = lg2f_(l1v) + (float)e1;
        float g2 = lg2f_(l2v) + (float)e2;
        float mm = fmaxf(g1, g2);
        float dd = fminf(g1, g2) - mm;
        float logv = mm + lg2f_(1.f + ex2f_(dd)) + ebsum;   // log2 P
        float per = -LN2 * logv;
        if (!(per < 1e29f)) per = 0.f;                 // zero_infinity (+inf/NaN)
        int den = tl < 1 ? 1 : tl;
        g_per_ex[b] = per / (float)den;
        __threadfence();
        unsigned pc = atomicAdd(&g_count, 1u);
        s_last = (pc == (unsigned)(B - 1)) ? 1u : 0u;
    }
    __syncthreads();

    // ---- last block computes the batch mean (deterministic fixed order) ----
    if (s_last && wid == 0) {
        float v = 0.f;
        for (int idx = wl; idx < B; idx += 32)
            v += *((volatile float*)&g_per_ex[idx]);
#pragma unroll
        for (int o = 16; o > 0; o >>= 1)
            v += __shfl_down_sync(FULLM, v, o);
        if (wl == 0) { out[0] = v / (float)B; g_count = 0u; }
    }
}

extern "C" void kernel_launch(void* const* d_in, const int* in_sizes, int n_in,
                              void* d_out, int out_size)
{
    const float* pred           = (const float*)d_in[0];
    const int*   targets        = (const int*)d_in[1];
    const int*   pred_lengths   = (const int*)d_in[2];
    const int*   target_lengths = (const int*)d_in[3];

    const int B = in_sizes[2];
    const int L = in_sizes[1] / B;
    const int C = 128;
    const int T = (in_sizes[0] / B) / C;

    ctc_forward_kernel<<<B, 96>>>(pred, targets, pred_lengths, target_lengths,
                                  (float*)d_out, T, C, L, B);
}

// round 12
// speedup vs baseline: 4.0817x; 1.1081x over previous
#include <cuda_runtime.h>
#include <cuda_bf16.h>

// CTC forward, LINEAR domain, per-thread exponent scaling, WARP-SPECIALIZED.
// One block (96 threads) per batch element:
//   warp 0   = consumer: lattice recurrence only (LDS ratios + shfl + FMA).
//   warps 1,2 = producers: emission ratios (LDG + ex2) into a double-buffered
//               smem ring; each handles 8 of every 16 steps. Producers also
//               produce the final partial chunk (time clamped), so the
//               consumer never touches gmem in the recurrence.
// Delayed renorm: max measured at group step 1, scale applied at step 3 --
// the fmax tree runs off the critical chain (bound: 2^96 < 2^127, exact).

#define LOG2E 1.4426950408889634f
#define LN2   0.6931471805599453f
#define FULLM 0xffffffffu
#define MAXB  4096
#define CH    16

__device__ float        g_per_ex[MAXB];
__device__ unsigned int g_count = 0;

__device__ __forceinline__ float ex2f_(float x){ float r; asm("ex2.approx.f32 %0,%1;" : "=f"(r) : "f"(x)); return r; }
__device__ __forceinline__ float lg2f_(float x){ float r; asm("lg2.approx.f32 %0,%1;" : "=f"(r) : "f"(x)); return r; }

__global__ __launch_bounds__(96, 1)
void ctc_forward_kernel(const float* __restrict__ pred,           // (B, T, C)
                        const int*   __restrict__ targets,        // (B, L)
                        const int*   __restrict__ pred_lengths,   // (B,)
                        const int*   __restrict__ target_lengths, // (B,)
                        float*       __restrict__ out,
                        int T, int C, int L, int B)
{
    __shared__ float4 ring[2][CH][32];     // [buf][step-in-chunk][lane]
    __shared__ float sE[129];
    __shared__ float sO[128];
    __shared__ int   sExp[32];
    __shared__ float s_eb[2];
    __shared__ unsigned int s_last;

    const int b   = blockIdx.x;
    const int tid = threadIdx.x;
    const int wid = tid >> 5;              // 0 consumer, 1..2 producers
    const int wl  = tid & 31;
    const int p0  = wl * 4;

    int   cols[4]; float sk[4], vm[4];
#pragma unroll
    for (int k = 0; k < 4; k++) {
        int p  = p0 + k;
        int li = (p < L) ? p : (L - 1);
        int l  = targets[(size_t)b * L + li];
        int pr = (li >= 1) ? targets[(size_t)b * L + li - 1] : -1;
        cols[k] = l;
        sk[k] = (l != 0 && l != pr) ? 1.f : 0.f;
        vm[k] = (p < L) ? 1.f : 0.f;
    }

    const float* rowp = pred + (size_t)b * T * C;
    int pl = pred_lengths[b];
    int Teff = pl < T ? pl : T; if (Teff < 1) Teff = 1;
    const int steps = Teff - 1;            // updates at t = 1..steps
    const int fc    = steps / CH;          // full chunks
    const int rem   = steps - fc * CH;     // partial-chunk length
    const int nchAll = fc + (rem ? 1 : 0);

    // ---- consumer state ----
    float E0=0.f,E1=0.f,E2=0.f,E3=0.f, O0=0.f,O1=0.f,O2=0.f,O3=0.f, EX=0.f;
    int   e_i = 0;
    float scale_in = 1.f;
    if (wid == 0 && wl == 0) {
        float eb0l2 = __ldg(rowp) * LOG2E;
        E0 = 1.f;
        O0 = ex2f_(fmaf(__ldg(rowp + cols[0]), LOG2E, -eb0l2)) * vm[0];
    }
    float rn_sc = 1.f; int rn_ee = 0;      // delayed renorm state

#define MEASURE()                                                            \
    {                                                                        \
        float m = fmaxf(fmaxf(fmaxf(E0,E1), fmaxf(E2,E3)),                   \
                        fmaxf(fmaxf(O0,O1), fmaxf(O2,O3)));                  \
        m = fmaxf(m, EX);                                                    \
        rn_ee = 0;                                                           \
        if (m > 0.f) rn_ee = (int)((__float_as_uint(m) >> 23) & 0xffu) - 127;\
        rn_sc = __uint_as_float((unsigned)(127 - rn_ee) << 23);              \
    }
#define APPLY()                                                              \
    {                                                                        \
        E0*=rn_sc; E1*=rn_sc; E2*=rn_sc; E3*=rn_sc;                          \
        O0*=rn_sc; O1*=rn_sc; O2*=rn_sc; O3*=rn_sc; EX*=rn_sc;               \
        e_i += rn_ee;                                                        \
        int ep = __shfl_up_sync(FULLM, e_i, 1);                              \
        int de = ep - e_i;                                                   \
        de = de > 126 ? 126 : (de < -126 ? -126 : de);                       \
        scale_in = __uint_as_float((unsigned)(127 + de) << 23);              \
    }

#define STEP(RX, RY, RZ, RW)                                                 \
    {                                                                        \
        float Om1 = __shfl_up_sync(FULLM, O3, 1);                            \
        Om1 = (wl == 0) ? 0.f : Om1 * scale_in;                              \
        float nO0 = fmaf(sk[0], Om1, O0 + E0) * (RX);                        \
        float nE0 = E0 + Om1;                                                \
        float nO1 = fmaf(sk[1], O0, O1 + E1) * (RY);                         \
        float nE1 = E1 + O0;                                                 \
        float nO2 = fmaf(sk[2], O1, O2 + E2) * (RZ);                         \
        float nE2 = E2 + O1;                                                 \
        float nO3 = fmaf(sk[3], O2, O3 + E3) * (RW);                         \
        float nE3 = E3 + O2;                                                 \
        float nEX = (wl == 31) ? (EX + O3) : 0.f;                            \
        O0=nO0; O1=nO1; O2=nO2; O3=nO3;                                      \
        E0=nE0; E1=nE1; E2=nE2; E3=nE3; EX=nEX;                              \
    }

    // ---- producer state: raw loads for share of chunk 0 ----
    float rb_[8], r0_[8], r1_[8], r2_[8], r3_[8];
    float pebs = 0.f;
    if (wid >= 1) {
        if (wid == 1) pebs = __ldg(rowp) * LOG2E;      // t = 0 blank term
#pragma unroll
        for (int jj = 0; jj < 8; jj++) {
            int tt = (wid - 1) * 8 + jj + 1;
            int tc = tt > steps ? steps : tt;
            const float* pp = rowp + (size_t)tc * C;
            rb_[jj] = __ldg(pp);
            r0_[jj] = __ldg(pp + cols[0]);
            r1_[jj] = __ldg(pp + cols[1]);
            r2_[jj] = __ldg(pp + cols[2]);
            r3_[jj] = __ldg(pp + cols[3]);
        }
    }

    // ---- phase loop: producers fill chunk p, consumer eats chunk p-1 ----
    for (int p = 0; p <= nchAll; p++) {
        if (wid >= 1) {
            if (p < nchAll) {
#pragma unroll
                for (int jj = 0; jj < 8; jj++) {
                    const int j = (wid - 1) * 8 + jj;
                    const int tglob = p * CH + j + 1;
                    float ebv = rb_[jj] * LOG2E;
                    float4 o;
                    o.x = ex2f_(fmaf(r0_[jj], LOG2E, -ebv)) * vm[0];
                    o.y = ex2f_(fmaf(r1_[jj], LOG2E, -ebv)) * vm[1];
                    o.z = ex2f_(fmaf(r2_[jj], LOG2E, -ebv)) * vm[2];
                    o.w = ex2f_(fmaf(r3_[jj], LOG2E, -ebv)) * vm[3];
                    ring[p & 1][j][wl] = o;
                    if (tglob <= steps) pebs += ebv;   // guard clamped dups
                }
#pragma unroll
                for (int jj = 0; jj < 8; jj++) {       // preload chunk p+1 share
                    int tn = (p + 1) * CH + (wid - 1) * 8 + jj + 1;
                    if (tn > steps) tn = steps;
                    const float* pp = rowp + (size_t)tn * C;
                    rb_[jj] = __ldg(pp);
                    r0_[jj] = __ldg(pp + cols[0]);
                    r1_[jj] = __ldg(pp + cols[1]);
                    r2_[jj] = __ldg(pp + cols[2]);
                    r3_[jj] = __ldg(pp + cols[3]);
                }
            }
        } else if (p >= 1) {
            const int cidx = p - 1;
            const int buf  = cidx & 1;
            if (cidx < fc) {
#pragma unroll
                for (int j = 0; j < CH; j++) {
                    float4 r = ring[buf][j][wl];
                    STEP(r.x, r.y, r.z, r.w);
                    if ((j & 3) == 1) MEASURE();       // off-chain
                    if ((j & 3) == 3) APPLY();         // 9 FMULs on chain
                }
            } else {
                for (int j = 0; j < rem; j++) {        // partial last chunk
                    float4 r = ring[buf][j][wl];
                    STEP(r.x, r.y, r.z, r.w);
                    MEASURE(); APPLY();                // immediate, cheap tail
                }
            }
        }
        __syncthreads();
    }
#undef STEP
#undef MEASURE
#undef APPLY

    // ---- gather + per-example loss ----
    if (wid == 0) {
        sO[p0+0]=O0; sO[p0+1]=O1; sO[p0+2]=O2; sO[p0+3]=O3;
        sE[p0+0]=E0; sE[p0+1]=E1; sE[p0+2]=E2; sE[p0+3]=E3;
        if (wl == 31) sE[128] = EX;
        sExp[wl] = e_i;
    } else if (wl == 0) {
        s_eb[wid - 1] = pebs;
    }
    __syncthreads();

    if (tid == 0) {
        float ebsum = s_eb[0] + s_eb[1];
        int tl = target_lengths[b];
        int tlc = tl; if (tlc < 1) tlc = 1; if (tlc > L) tlc = L;
        float l1v = sO[tlc - 1];                       // state 2*tl - 1
        int   e1  = sExp[(tlc - 1) >> 2];
        float l2v = sE[tlc];                           // state 2*tl
        int   e2  = (tlc < 128) ? sExp[tlc >> 2] : sExp[31];
        float g1 = lg2f_(l1v) + (float)e1;
        float g2 = lg2f_(l2v) + (float)e2;
        float mm = fmaxf(g1, g2);
        float dd = fminf(g1, g2) - mm;
        float logv = mm + lg2f_(1.f + ex2f_(dd)) + ebsum;   // log2 P
        float per = -LN2 * logv;
        if (!(per < 1e29f)) per = 0.f;                 // zero_infinity (+inf/NaN)
        int den = tl < 1 ? 1 : tl;
        g_per_ex[b] = per / (float)den;
        __threadfence();
        unsigned pc = atomicAdd(&g_count, 1u);
        s_last = (pc == (unsigned)(B - 1)) ? 1u : 0u;
    }
    __syncthreads();

    // ---- last block computes the batch mean (deterministic fixed order) ----
    if (s_last && wid == 0) {
        float v = 0.f;
        for (int idx = wl; idx < B; idx += 32)
            v += *((volatile float*)&g_per_ex[idx]);
#pragma unroll
        for (int o = 16; o > 0; o >>= 1)
            v += __shfl_down_sync(FULLM, v, o);
        if (wl == 0) { out[0] = v / (float)B; g_count = 0u; }
    }
}

extern "C" void kernel_launch(void* const* d_in, const int* in_sizes, int n_in,
                              void* d_out, int out_size)
{
    const float* pred           = (const float*)d_in[0];
    const int*   targets        = (const int*)d_in[1];
    const int*   pred_lengths   = (const int*)d_in[2];
    const int*   target_lengths = (const int*)d_in[3];

    const int B = in_sizes[2];
    const int L = in_sizes[1] / B;
    const int C = 128;
    const int T = (in_sizes[0] / B) / C;

    ctc_forward_kernel<<<B, 96>>>(pred, targets, pred_lengths, target_lengths,
                                  (float*)d_out, T, C, L, B);
}

// round 13
// speedup vs baseline: 4.6115x; 1.1298x over previous
#include <cuda_runtime.h>
#include <cuda_bf16.h>

// CTC forward, LINEAR domain, per-thread exponent scaling, WARP-SPECIALIZED,
// PACKED f32x2 lattice arithmetic.
// One block (96 threads) per batch element:
//   warp 0   = consumer: lattice recurrence (LDS ratios + shfl + f32x2 FMA).
//   warps 1,2 = producers: emission ratios (LDG + ex2) into a double-buffered
//               smem ring; each handles 16 of every 32 steps, incl. the final
//               partial chunk (time clamped) -> consumer never touches gmem.
// One __syncthreads per 32 steps. Delayed renorm (measure j%4==1, apply j%4==3).

#define LOG2E 1.4426950408889634f
#define LN2   0.6931471805599453f
#define FULLM 0xffffffffu
#define MAXB  4096
#define CH    32

__device__ float        g_per_ex[MAXB];
__device__ unsigned int g_count = 0;

typedef unsigned long long u64;

__device__ __forceinline__ float ex2f_(float x){ float r; asm("ex2.approx.f32 %0,%1;" : "=f"(r) : "f"(x)); return r; }
__device__ __forceinline__ float lg2f_(float x){ float r; asm("lg2.approx.f32 %0,%1;" : "=f"(r) : "f"(x)); return r; }

__device__ __forceinline__ u64  PK2(float lo, float hi){ u64 r; asm("mov.b64 %0,{%1,%2};" : "=l"(r) : "f"(lo), "f"(hi)); return r; }
__device__ __forceinline__ void UPK(u64 v, float& lo, float& hi){ asm("mov.b64 {%0,%1},%2;" : "=f"(lo), "=f"(hi) : "l"(v)); }
__device__ __forceinline__ u64  ADD2(u64 a, u64 b){ u64 r; asm("add.rn.f32x2 %0,%1,%2;" : "=l"(r) : "l"(a), "l"(b)); return r; }
__device__ __forceinline__ u64  MUL2(u64 a, u64 b){ u64 r; asm("mul.rn.f32x2 %0,%1,%2;" : "=l"(r) : "l"(a), "l"(b)); return r; }
__device__ __forceinline__ u64  FMA2(u64 a, u64 b, u64 c){ u64 r; asm("fma.rn.f32x2 %0,%1,%2,%3;" : "=l"(r) : "l"(a), "l"(b), "l"(c)); return r; }

__global__ __launch_bounds__(96, 1)
void ctc_forward_kernel(const float* __restrict__ pred,           // (B, T, C)
                        const int*   __restrict__ targets,        // (B, L)
                        const int*   __restrict__ pred_lengths,   // (B,)
                        const int*   __restrict__ target_lengths, // (B,)
                        float*       __restrict__ out,
                        int T, int C, int L, int B)
{
    __shared__ float4 ring[2][CH][32];     // [buf][step-in-chunk][lane] (32 KB)
    __shared__ float sE[129];
    __shared__ float sO[128];
    __shared__ int   sExp[32];
    __shared__ float s_eb[2];
    __shared__ unsigned int s_last;

    const int b   = blockIdx.x;
    const int tid = threadIdx.x;
    const int wid = tid >> 5;              // 0 consumer, 1..2 producers
    const int wl  = tid & 31;
    const int p0  = wl * 4;

    int   cols[4]; float skv[4], vm[4];
#pragma unroll
    for (int k = 0; k < 4; k++) {
        int p  = p0 + k;
        int li = (p < L) ? p : (L - 1);
        int l  = targets[(size_t)b * L + li];
        int pr = (li >= 1) ? targets[(size_t)b * L + li - 1] : -1;
        cols[k] = l;
        skv[k] = (l != 0 && l != pr) ? 1.f : 0.f;
        vm[k]  = (p < L) ? 1.f : 0.f;
    }
    const u64 SKa = PK2(skv[0], skv[1]);
    const u64 SKb = PK2(skv[2], skv[3]);

    const float* rowp = pred + (size_t)b * T * C;
    int pl = pred_lengths[b];
    int Teff = pl < T ? pl : T; if (Teff < 1) Teff = 1;
    const int steps = Teff - 1;            // updates at t = 1..steps
    const int fc    = steps / CH;          // full chunks
    const int rem   = steps - fc * CH;     // partial-chunk length
    const int nchAll = fc + (rem ? 1 : 0);

    // ---- consumer state (packed) ----
    u64 Oa = 0, Ob = 0, Ea = 0, Eb = 0;    // (0.f,0.f) packed
    float EX = 0.f;
    int   e_i = 0;
    float scale_in = (wl == 0) ? 0.f : 1.f;
    if (wid == 0 && wl == 0) {
        float eb0l2 = __ldg(rowp) * LOG2E;
        float o0 = ex2f_(fmaf(__ldg(rowp + cols[0]), LOG2E, -eb0l2)) * vm[0];
        Ea = PK2(1.f, 0.f);
        Oa = PK2(o0, 0.f);
    }
    float rn_sc = 1.f; int rn_ee = 0;      // delayed renorm state

#define STEP(R4)                                                             \
    {                                                                        \
        float o0, o1, o2, o3; UPK(Oa, o0, o1); UPK(Ob, o2, o3);              \
        float Om1 = __shfl_up_sync(FULLM, o3, 1) * scale_in;                 \
        u64 Sa = PK2(Om1, o0);                                               \
        u64 Sb = PK2(o1, o2);                                                \
        u64 Ra = PK2((R4).x, (R4).y);                                        \
        u64 Rb = PK2((R4).z, (R4).w);                                        \
        u64 ta = ADD2(Oa, Ea);                                               \
        u64 tb = ADD2(Ob, Eb);                                               \
        Oa = MUL2(FMA2(SKa, Sa, ta), Ra);                                    \
        Ob = MUL2(FMA2(SKb, Sb, tb), Rb);                                    \
        Ea = ADD2(Ea, Sa);                                                   \
        Eb = ADD2(Eb, Sb);                                                   \
        EX += o3;                                                            \
    }
#define MEASURE()                                                            \
    {                                                                        \
        float o0, o1, o2, o3, e0, e1, e2, e3;                                \
        UPK(Oa, o0, o1); UPK(Ob, o2, o3);                                    \
        UPK(Ea, e0, e1); UPK(Eb, e2, e3);                                    \
        float m = fmaxf(fmaxf(fmaxf(e0, e1), fmaxf(e2, e3)),                 \
                        fmaxf(fmaxf(o0, o1), fmaxf(o2, o3)));                \
        m = fmaxf(m, EX);                                                    \
        rn_ee = 0;                                                           \
        if (m > 0.f) rn_ee = (int)((__float_as_uint(m) >> 23) & 0xffu) - 127;\
        rn_sc = __uint_as_float((unsigned)(127 - rn_ee) << 23);              \
    }
#define APPLY()                                                              \
    {                                                                        \
        u64 SC = PK2(rn_sc, rn_sc);                                          \
        Oa = MUL2(Oa, SC); Ob = MUL2(Ob, SC);                                \
        Ea = MUL2(Ea, SC); Eb = MUL2(Eb, SC);                                \
        EX *= rn_sc;                                                         \
        e_i += rn_ee;                                                        \
        int ep = __shfl_up_sync(FULLM, e_i, 1);                              \
        int de = ep - e_i;                                                   \
        de = de > 126 ? 126 : (de < -126 ? -126 : de);                       \
        scale_in = (wl == 0) ? 0.f                                           \
                 : __uint_as_float((unsigned)(127 + de) << 23);              \
    }

    // ---- producer state: raw loads for share of chunk 0 ----
    float rb_[16], r0_[16], r1_[16], r2_[16], r3_[16];
    float pebs = 0.f;
    if (wid >= 1) {
        if (wid == 1) pebs = __ldg(rowp) * LOG2E;      // t = 0 blank term
#pragma unroll
        for (int jj = 0; jj < 16; jj++) {
            int tt = (wid - 1) * 16 + jj + 1;
            int tc = tt > steps ? steps : tt;
            const float* pp = rowp + (size_t)tc * C;
            rb_[jj] = __ldg(pp);
            r0_[jj] = __ldg(pp + cols[0]);
            r1_[jj] = __ldg(pp + cols[1]);
            r2_[jj] = __ldg(pp + cols[2]);
            r3_[jj] = __ldg(pp + cols[3]);
        }
    }

    // ---- phase loop: producers fill chunk p, consumer eats chunk p-1 ----
    for (int p = 0; p <= nchAll; p++) {
        if (wid >= 1) {
            if (p < nchAll) {
#pragma unroll
                for (int jj = 0; jj < 16; jj++) {
                    const int j = (wid - 1) * 16 + jj;
                    const int tglob = p * CH + j + 1;
                    float ebv = rb_[jj] * LOG2E;
                    float4 o;
                    o.x = ex2f_(fmaf(r0_[jj], LOG2E, -ebv)) * vm[0];
                    o.y = ex2f_(fmaf(r1_[jj], LOG2E, -ebv)) * vm[1];
                    o.z = ex2f_(fmaf(r2_[jj], LOG2E, -ebv)) * vm[2];
                    o.w = ex2f_(fmaf(r3_[jj], LOG2E, -ebv)) * vm[3];
                    ring[p & 1][j][wl] = o;
                    if (tglob <= steps) pebs += ebv;   // guard clamped dups
                }
#pragma unroll
                for (int jj = 0; jj < 16; jj++) {      // preload chunk p+1 share
                    int tn = (p + 1) * CH + (wid - 1) * 16 + jj + 1;
                    if (tn > steps) tn = steps;
                    const float* pp = rowp + (size_t)tn * C;
                    rb_[jj] = __ldg(pp);
                    r0_[jj] = __ldg(pp + cols[0]);
                    r1_[jj] = __ldg(pp + cols[1]);
                    r2_[jj] = __ldg(pp + cols[2]);
                    r3_[jj] = __ldg(pp + cols[3]);
                }
            }
        } else if (p >= 1) {
            const int cidx = p - 1;
            const int buf  = cidx & 1;
            if (cidx < fc) {
#pragma unroll
                for (int j = 0; j < CH; j++) {
                    float4 r = ring[buf][j][wl];
                    STEP(r);
                    if ((j & 3) == 1) MEASURE();       // off-chain
                    if ((j & 3) == 3) APPLY();         // on-chain: 4 MUL2 + EX
                }
            } else {
                for (int j = 0; j < rem; j++) {        // partial last chunk
                    float4 r = ring[buf][j][wl];
                    STEP(r);
                    if ((j & 3) == 1) MEASURE();
                    if ((j & 3) == 3) APPLY();
                }
            }
        }
        __syncthreads();
    }
#undef STEP
#undef MEASURE
#undef APPLY

    // ---- gather + per-example loss ----
    if (wid == 0) {
        float o0, o1, o2, o3, e0, e1, e2, e3;
        UPK(Oa, o0, o1); UPK(Ob, o2, o3);
        UPK(Ea, e0, e1); UPK(Eb, e2, e3);
        sO[p0+0]=o0; sO[p0+1]=o1; sO[p0+2]=o2; sO[p0+3]=o3;
        sE[p0+0]=e0; sE[p0+1]=e1; sE[p0+2]=e2; sE[p0+3]=e3;
        if (wl == 31) sE[128] = EX;
        sExp[wl] = e_i;
    } else if (wl == 0) {
        s_eb[wid - 1] = pebs;
    }
    __syncthreads();

    if (tid == 0) {
        float ebsum = s_eb[0] + s_eb[1];
        int tl = target_lengths[b];
        int tlc = tl; if (tlc < 1) tlc = 1; if (tlc > L) tlc = L;
        float l1v = sO[tlc - 1];                       // state 2*tl - 1
        int   e1x = sExp[(tlc - 1) >> 2];
        float l2v = sE[tlc];                           // state 2*tl
        int   e2x = (tlc < 128) ? sExp[tlc >> 2] : sExp[31];
        float g1 = lg2f_(l1v) + (float)e1x;
        float g2 = lg2f_(l2v) + (float)e2x;
        float mm = fmaxf(g1, g2);
        float dd = fminf(g1, g2) - mm;
        float logv = mm + lg2f_(1.f + ex2f_(dd)) + ebsum;   // log2 P
        float per = -LN2 * logv;
        if (!(per < 1e29f)) per = 0.f;                 // zero_infinity (+inf/NaN)
        int den = tl < 1 ? 1 : tl;
        g_per_ex[b] = per / (float)den;
        __threadfence();
        unsigned pc = atomicAdd(&g_count, 1u);
        s_last = (pc == (unsigned)(B - 1)) ? 1u : 0u;
    }
    __syncthreads();

    // ---- last block computes the batch mean (deterministic fixed order) ----
    if (s_last && wid == 0) {
        float v = 0.f;
        for (int idx = wl; idx < B; idx += 32)
            v += *((volatile float*)&g_per_ex[idx]);
#pragma unroll
        for (int o = 16; o > 0; o >>= 1)
            v += __shfl_down_sync(FULLM, v, o);
        if (wl == 0) { out[0] = v / (float)B; g_count = 0u; }
    }
}

extern "C" void kernel_launch(void* const* d_in, const int* in_sizes, int n_in,
                              void* d_out, int out_size)
{
    const float* pred           = (const float*)d_in[0];
    const int*   targets        = (const int*)d_in[1];
    const int*   pred_lengths   = (const int*)d_in[2];
    const int*   target_lengths = (const int*)d_in[3];

    const int B = in_sizes[2];
    const int L = in_sizes[1] / B;
    const int C = 128;
    const int T = (in_sizes[0] / B) / C;

    ctc_forward_kernel<<<B, 96>>>(pred, targets, pred_lengths, target_lengths,
                                  (float*)d_out, T, C, L, B);
}